// round 9
// baseline (speedup 1.0000x reference)
#include <cuda_runtime.h>

// ---------------------------------------------------------------------------
// BottomUpHTMM — complete 4-ary tree depth 7, single persistent kernel.
// 128 blocks x 512 threads; each block owns two level-4 subtrees.
// Redundant top (levels 2/1/0) per block. float4-vectorized dots.
// dntab built in the c2-wait shadow. acquire/release PTX sync.
// ---------------------------------------------------------------------------

#define GC    128
#define NBLK  128

// tables
__device__ float g_asp [4096];      // a_sp[g][i][l][j]   (wt=g*8+i -> wt*32+l*8+j)
__device__ float g_loga[4096];      // log sm_a
__device__ float g_bt  [16*256*8];  // sm_b[g][m][c]
__device__ float g_lbt [16*256*8];
__device__ float g_pit [512];       // sm_pi[g][pos][c]
__device__ float g_lpit[512];
__device__ float g_lsp [64];        // log sm_sp[g][l]

// leaf contribution tables: index (l*256+lab)*128 + wt
__device__ float g_uptab[1024 * GC];
__device__ float g_dntab[1024 * GC];

// cross-block state
__device__ float g_beta4 [256 * GC];
__device__ float g_beta3 [64 * GC];
__device__ float g_sbeta3[64 * GC];
__device__ float g_accum [16];

// sync state
__device__ unsigned g_cnt = 0;
__device__ unsigned g_gen = 0;
__device__ unsigned g_f1[NBLK];     // beta4 pair of block s ready
__device__ unsigned g_c2;           // # lvl3 nodes done
__device__ unsigned g_cdn;          // # blocks done building dntab
__device__ unsigned g_cfin;         // finish ticket

// shared-memory layout (floats; rows of 128)
#define OFF_B6    0        // 32 rows lvl6 beta
#define OFF_S6    4096     // 32 rows lvl6 sbeta
#define OFF_B5    8192     // 8 rows lvl5 beta
#define OFF_S5    9216     // 8 rows lvl5 sbeta
#define OFF_S4    10240    // 2 rows lvl4 sbeta
#define OFF_E5    10496    // 8 rows lvl5 eps
#define OFF_E6    11520    // 32 rows lvl6 eps
#define OFF_TOP   15616    // 64 rows beta3 copy
#define OFF_B2    23808    // 16 rows lvl2 beta
#define OFF_S2    25856    // 16 rows lvl2 sbeta
#define OFF_B1    27904    // 4 rows lvl1 beta
#define OFF_S1    28416    // 4 rows lvl1 sbeta
#define OFF_E1    28928    // 4 rows lvl1 eps
#define OFF_E2    29440    // 16 rows lvl2 eps
#define OFF_E3    31488    // 1 row  own lvl3 eps
#define OFF_E4    31616    // 2 rows own lvl4 eps
#define OFF_RED   31872    // 64
#define OFF_LAB   31936    // 208 ints
#define OFF_LAST  32144    // 1
#define SMEM_FLOATS 32148  // ~125.6 KB

__device__ __forceinline__ float sum8(float v) {
    v += __shfl_xor_sync(0xffffffffu, v, 4);
    v += __shfl_xor_sync(0xffffffffu, v, 2);
    v += __shfl_xor_sync(0xffffffffu, v, 1);
    return v;
}

__device__ __forceinline__ void load_tab(const float* __restrict__ base, int wt,
                                         float (&r)[4][8]) {
    const float4* p = (const float4*)(base + wt * 32);
    #pragma unroll
    for (int l = 0; l < 4; l++) {
        float4 a = p[2*l], b = p[2*l + 1];
        r[l][0]=a.x; r[l][1]=a.y; r[l][2]=a.z; r[l][3]=a.w;
        r[l][4]=b.x; r[l][5]=b.y; r[l][6]=b.z; r[l][7]=b.w;
    }
}

// ---- acquire/release helpers ----
__device__ __forceinline__ void st_release(unsigned* p, unsigned v) {
    asm volatile("st.release.gpu.global.u32 [%0], %1;" :: "l"(p), "r"(v) : "memory");
}
__device__ __forceinline__ unsigned ld_acquire(unsigned* p) {
    unsigned v;
    asm volatile("ld.acquire.gpu.global.u32 %0, [%1];" : "=r"(v) : "l"(p) : "memory");
    return v;
}
__device__ __forceinline__ void red_release_add(unsigned* p, unsigned v) {
    asm volatile("red.release.gpu.global.add.u32 [%0], %1;" :: "l"(p), "r"(v) : "memory");
}
__device__ __forceinline__ unsigned atom_acqrel_add(unsigned* p, unsigned v) {
    unsigned old;
    asm volatile("atom.acq_rel.gpu.global.add.u32 %0, [%1], %2;"
                 : "=r"(old) : "l"(p), "r"(v) : "memory");
    return old;
}

// full grid barrier (NBLK blocks co-resident)
__device__ __forceinline__ void gbar() {
    __syncthreads();
    if (threadIdx.x == 0) {
        unsigned gen = ld_acquire(&g_gen);
        unsigned old = atom_acqrel_add(&g_cnt, 1u);
        if (old == NBLK - 1u) {
            asm volatile("st.relaxed.gpu.global.u32 [%0], %1;" :: "l"(&g_cnt), "r"(0u) : "memory");
            st_release(&g_gen, gen + 1u);
        } else {
            while (ld_acquire(&g_gen) == gen) __nanosleep(32);
        }
    }
    __syncthreads();
}

// float4-vectorized up-dot over 4 children rows (stride 128 floats)
__device__ __forceinline__ float dot_up(const float* __restrict__ cb0,
                                        const float (&as)[4][8], int g) {
    float sb = 0.f;
    #pragma unroll
    for (int l = 0; l < 4; l++) {
        const float4* p = (const float4*)(cb0 + l*128 + g*8);
        float4 x = p[0], y = p[1];
        sb += as[l][0]*x.x + as[l][1]*x.y + as[l][2]*x.z + as[l][3]*x.w
            + as[l][4]*y.x + as[l][5]*y.y + as[l][6]*y.z + as[l][7]*y.w;
    }
    return sb;
}

// float4-vectorized down-dot for one child row
__device__ __forceinline__ void dot_dn(const float* __restrict__ row,
                                       const float (&as)[4][8],
                                       const float (&la)[4][8],
                                       int g, int l, float& ce, float& ca) {
    const float4* p = (const float4*)(row + g*8);
    float4 x = p[0], y = p[1];
    ce = as[l][0]*x.x + as[l][1]*x.y + as[l][2]*x.z + as[l][3]*x.w
       + as[l][4]*y.x + as[l][5]*y.y + as[l][6]*y.z + as[l][7]*y.w;
    ca = la[l][0]*x.x + la[l][1]*x.y + la[l][2]*x.z + la[l][3]*x.w
       + la[l][4]*y.x + la[l][5]*y.y + la[l][6]*y.z + la[l][7]*y.w;
}

__global__ void __launch_bounds__(512, 1)
main_kernel(const int* __restrict__ tn,
            const float* __restrict__ a,
            const float* __restrict__ b,
            const float* __restrict__ pi,
            const float* __restrict__ sp,
            float* __restrict__ out)
{
    extern __shared__ float sm[];
    const int tid = threadIdx.x, s = blockIdx.x;
    const int q = tid >> 7, wt = tid & 127, g = wt >> 3, i = wt & 7;
    int* slab = (int*)(sm + OFF_LAB);

    // ---- stage labels ----
    if (tid < 193) {
        int idx = tid, node;
        if      (idx < 128) node = 5461 + 128*s + idx;
        else if (idx < 160) node = 1365 + 32*s + (idx - 128);
        else if (idx < 168) node = 341 + 8*s + (idx - 160);
        else if (idx < 170) node = 85 + 2*s + (idx - 168);
        else if (idx == 170) node = (s < 64) ? (21 + s) : 21;
        else if (idx < 192) node = idx - 171;          // top nodes 0..20
        else                node = 21 + (s >> 1);      // own lvl3 ancestor
        slab[idx] = tn[node * 7];
    }
    // ---- reset flags (pre-gbar, ordered by gbar) ----
    if (tid == 0) {
        g_f1[s] = 0u;
        if (s == 0) g_c2 = 0u;
        if (s == 1) g_cfin = 0u;
        if (s == 2) g_cdn = 0u;
    }

    // ================= phase 0a: softmax prep =================
    if (s < 16) {
        if (tid < 256) {
            int w = tid >> 5, ln = tid & 31;
            const float* bp = b + (s*8 + w) * 256;
            float mx = -1e30f;
            for (int m = ln; m < 256; m += 32) mx = fmaxf(mx, bp[m]);
            #pragma unroll
            for (int o = 16; o; o >>= 1) mx = fmaxf(mx, __shfl_xor_sync(0xffffffffu, mx, o));
            float ssum = 0.f;
            for (int m = ln; m < 256; m += 32) ssum += expf(bp[m] - mx);
            #pragma unroll
            for (int o = 16; o; o >>= 1) ssum += __shfl_xor_sync(0xffffffffu, ssum, o);
            float inv = 1.f / ssum, ls = logf(ssum);
            for (int m = ln; m < 256; m += 32) {
                float e = bp[m] - mx;
                g_bt [s*2048 + m*8 + w] = expf(e) * inv;
                g_lbt[s*2048 + m*8 + w] = e - ls;
            }
        }
    } else if (s == 16) {
        float* s_sp = sm + OFF_RED;
        if (tid < 16) {
            float v[4]; float mx = -1e30f;
            #pragma unroll
            for (int l = 0; l < 4; l++) { v[l] = sp[tid*4 + l]; mx = fmaxf(mx, v[l]); }
            float su = 0.f;
            #pragma unroll
            for (int l = 0; l < 4; l++) { v[l] = expf(v[l] - mx); su += v[l]; }
            float inv = 1.f / su;
            #pragma unroll
            for (int l = 0; l < 4; l++) {
                float smv = v[l] * inv;
                s_sp[tid*4 + l]  = smv;
                g_lsp[tid*4 + l] = logf(smv);
            }
        }
        if (tid < 64) {
            int gg = tid >> 2, l = tid & 3;
            float v[8]; float mx = -1e30f;
            #pragma unroll
            for (int c = 0; c < 8; c++) { v[c] = pi[gg*32 + c*4 + l]; mx = fmaxf(mx, v[c]); }
            float su = 0.f;
            #pragma unroll
            for (int c = 0; c < 8; c++) { v[c] = expf(v[c] - mx); su += v[c]; }
            float inv = 1.f / su, ls = logf(su);
            #pragma unroll
            for (int c = 0; c < 8; c++) {
                g_pit [gg*32 + l*8 + c] = v[c] * inv;
                g_lpit[gg*32 + l*8 + c] = logf(v[c]) - ls;
            }
        }
        __syncthreads();
        {   // sm_a: 512 (g,j,l) groups, one per thread
            int gg = tid >> 5, j = (tid >> 2) & 7, l = tid & 3;
            float v[8]; float mx = -1e30f;
            #pragma unroll
            for (int ii = 0; ii < 8; ii++) {
                v[ii] = a[gg*256 + ii*32 + j*4 + l];
                mx = fmaxf(mx, v[ii]);
            }
            float su = 0.f;
            #pragma unroll
            for (int ii = 0; ii < 8; ii++) { v[ii] = expf(v[ii] - mx); su += v[ii]; }
            float inv = 1.f / su, ls = logf(su);
            float spv = s_sp[gg*4 + l];
            #pragma unroll
            for (int ii = 0; ii < 8; ii++) {
                int idx = ((gg*8 + ii)*4 + l)*8 + j;
                g_asp [idx] = v[ii] * inv * spv;
                g_loga[idx] = logf(v[ii]) - ls;
            }
        }
    } else if (s == 17) {
        if (tid < 16) g_accum[tid] = 0.f;
    }
    gbar();

    // as + lsp in registers
    float as[4][8];
    load_tab(g_asp, wt, as);
    float lsp[4];
    #pragma unroll
    for (int l = 0; l < 4; l++) lsp[l] = g_lsp[g*4 + l];

    // ================= phase 0b: uptab ONLY (dntab deferred) =================
    #pragma unroll
    for (int r = 0; r < 2; r++) {
        int t = (s*4 + q) + 512*r;
        int l = t >> 8, lab = t & 255;
        float lb = g_pit[g*32 + l*8 + i] * g_bt[g*2048 + lab*8 + i];
        lb = __fdividef(lb, sum8(lb));
        float ce = 0.f;
        #pragma unroll
        for (int j = 0; j < 8; j++)
            ce += as[l][j] * __shfl_sync(0xffffffffu, lb, j, 8);
        g_uptab[t*128 + wt] = ce;
    }
    gbar();

    // ================= phase 1: pair-of-subtrees up =================
    float emis6[8];
    #pragma unroll
    for (int rr = 0; rr < 8; rr++)
        emis6[rr] = g_bt[g*2048 + slab[128 + rr*4 + q]*8 + i];
    #pragma unroll 4
    for (int rr = 0; rr < 8; rr++) {
        int k = rr*4 + q;
        int lab0 = slab[4*k], lab1 = slab[4*k+1], lab2 = slab[4*k+2], lab3 = slab[4*k+3];
        float sb = g_uptab[(0*256 + lab0)*128 + wt]
                 + g_uptab[(1*256 + lab1)*128 + wt]
                 + g_uptab[(2*256 + lab2)*128 + wt]
                 + g_uptab[(3*256 + lab3)*128 + wt];
        float tmp = emis6[rr] * sb;
        float ts = sum8(tmp);
        sm[OFF_B6 + k*128 + wt] = __fdividef(tmp, ts);
        sm[OFF_S6 + k*128 + wt] = sb;
    }
    __syncthreads();
    // lvl5 (8)
    #pragma unroll
    for (int rr = 0; rr < 2; rr++) {
        int k = rr*4 + q;
        float sb = dot_up(sm + OFF_B6 + 4*k*128, as, g);
        float tmp = g_bt[g*2048 + slab[160 + k]*8 + i] * sb;
        float ts = sum8(tmp);
        sm[OFF_B5 + k*128 + wt] = __fdividef(tmp, ts);
        sm[OFF_S5 + k*128 + wt] = sb;
    }
    __syncthreads();
    // lvl4 (2, q<2) -> global beta4
    if (q < 2) {
        int t4 = 2*s + q;
        float sb = dot_up(sm + OFF_B5 + 4*q*128, as, g);
        float tmp = g_bt[g*2048 + slab[168 + q]*8 + i] * sb;
        float ts = sum8(tmp);
        g_beta4[t4*128 + wt] = __fdividef(tmp, ts);
        sm[OFF_S4 + q*128 + wt] = sb;
    }
    __syncthreads();
    if (tid == 0) st_release(&g_f1[s], 1u);

    // ================= lvl3 up (blocks 0..63) =================
    if (s < 64) {
        if (tid == 0) {
            while (ld_acquire(&g_f1[2*s])     == 0u) {}
            while (ld_acquire(&g_f1[2*s + 1]) == 0u) {}
        }
        __syncthreads();
        if (q == 0) {
            float sb = dot_up(&g_beta4[4*s*128], as, g);
            float tmp = g_bt[g*2048 + slab[170]*8 + i] * sb;
            float ts = sum8(tmp);
            g_beta3 [s*128 + wt] = __fdividef(tmp, ts);
            g_sbeta3[s*128 + wt] = sb;
        }
        __syncthreads();
        if (tid == 0) red_release_add(&g_c2, 1u);
    }

    // ================= dntab build (c2-wait shadow) =================
    #pragma unroll
    for (int r = 0; r < 2; r++) {
        int t = (s*4 + q) + 512*r;
        int l = t >> 8, lab = t & 255;
        const float4* lp = (const float4*)(g_loga + wt*32 + l*8);
        float4 y0 = lp[0], y1 = lp[1];
        float lav[8] = {y0.x, y0.y, y0.z, y0.w, y1.x, y1.y, y1.z, y1.w};
        float lb = g_pit[g*32 + l*8 + i] * g_bt[g*2048 + lab*8 + i];
        lb = __fdividef(lb, sum8(lb));
        float ce = 0.f, ca = 0.f;
        #pragma unroll
        for (int j = 0; j < 8; j++) {
            float v = __shfl_sync(0xffffffffu, lb, j, 8);
            ce += as[l][j]*v; ca += as[l][j]*lav[j]*v;
        }
        float w = lsp[l] + g_lpit[g*32 + l*8 + i] + g_lbt[g*2048 + lab*8 + i];
        g_dntab[t*128 + wt] = ca + w*ce;
    }
    __syncthreads();
    if (tid == 0) red_release_add(&g_cdn, 1u);

    // la table (also in the shadow)
    float la[4][8];
    load_tab(g_loga, wt, la);
    #pragma unroll
    for (int l = 0; l < 4; l++)
        #pragma unroll
        for (int j = 0; j < 8; j++) la[l][j] *= as[l][j];

    // ================= wait all lvl3 ready =================
    if (tid == 0) {
        while (ld_acquire(&g_c2) != 64u) __nanosleep(64);
    }
    __syncthreads();

    // copy all 64 beta3 rows to smem
    {
        float4* dst = (float4*)(sm + OFF_TOP);
        const float4* src = (const float4*)g_beta3;
        #pragma unroll
        for (int r = 0; r < 4; r++) dst[tid + r*512] = src[tid + r*512];
    }
    __syncthreads();

    // ================= redundant top: up lvl2/lvl1/root =================
    float acc = 0.f;
    #pragma unroll 2
    for (int rr = 0; rr < 4; rr++) {
        int k = rr*4 + q;
        float sb = dot_up(sm + OFF_TOP + 4*k*128, as, g);
        float tmp = g_bt[g*2048 + slab[176 + k]*8 + i] * sb;
        float ts = sum8(tmp);
        sm[OFF_B2 + k*128 + wt] = __fdividef(tmp, ts);
        sm[OFF_S2 + k*128 + wt] = sb;
    }
    __syncthreads();
    {
        float sb = dot_up(sm + OFF_B2 + 4*q*128, as, g);
        float tmp = g_bt[g*2048 + slab[172 + q]*8 + i] * sb;
        float ts = sum8(tmp);
        sm[OFF_B1 + q*128 + wt] = __fdividef(tmp, ts);
        sm[OFF_S1 + q*128 + wt] = sb;
    }
    __syncthreads();
    // root up+down (group 0)
    if (q == 0) {
        float sb = dot_up(sm + OFF_B1, as, g);
        int lab0 = slab[171];
        float tmp = g_bt[g*2048 + lab0*8 + i] * sb;
        float ts = sum8(tmp);
        float betar = __fdividef(tmp, ts);
        float pe = __fdividef(betar, sb);
        if (s == 0) acc += betar * g_lbt[g*2048 + lab0*8 + i];
        #pragma unroll
        for (int l = 0; l < 4; l++) {
            float ce, ca;
            dot_dn(sm + OFF_B1 + l*128, as, la, g, l, ce, ca);
            ce *= pe;
            sm[OFF_E1 + l*128 + wt] = ce;
            if (s == 0) acc += pe*ca + lsp[l]*ce;
        }
    }
    __syncthreads();
    // down lvl1 (group q = node q)
    {
        float epsv = sm[OFF_E1 + q*128 + wt];
        float pe = __fdividef(epsv, sm[OFF_S1 + q*128 + wt]);
        if (s == 0) acc += epsv * g_lbt[g*2048 + slab[172 + q]*8 + i];
        #pragma unroll
        for (int l = 0; l < 4; l++) {
            float ce, ca;
            dot_dn(sm + OFF_B2 + (4*q + l)*128, as, la, g, l, ce, ca);
            ce *= pe;
            sm[OFF_E2 + (4*q + l)*128 + wt] = ce;
            if (s == 0) acc += pe*ca + lsp[l]*ce;
        }
    }
    __syncthreads();
    // down lvl2: block0 full (acc); others own node only
    if (s == 0) {
        #pragma unroll 2
        for (int rr = 0; rr < 4; rr++) {
            int k = rr*4 + q;
            float epsv = sm[OFF_E2 + k*128 + wt];
            float pe = __fdividef(epsv, sm[OFF_S2 + k*128 + wt]);
            acc += epsv * g_lbt[g*2048 + slab[176 + k]*8 + i];
            #pragma unroll
            for (int l = 0; l < 4; l++) {
                float ce, ca;
                dot_dn(sm + OFF_TOP + (4*k + l)*128, as, la, g, l, ce, ca);
                ce *= pe;
                acc += pe*ca + lsp[l]*ce;
                if (4*k + l == 0) sm[OFF_E3 + wt] = ce;
            }
        }
    } else if (q == 0) {
        int t = s >> 1, p2 = t >> 2, lc = t & 3;
        float epsv = sm[OFF_E2 + p2*128 + wt];
        float pe = __fdividef(epsv, sm[OFF_S2 + p2*128 + wt]);
        const float4* p = (const float4*)(sm + OFF_TOP + (4*p2 + lc)*128 + g*8);
        float4 x = p[0], y = p[1];
        float ce = as[lc][0]*x.x + as[lc][1]*x.y + as[lc][2]*x.z + as[lc][3]*x.w
                 + as[lc][4]*y.x + as[lc][5]*y.y + as[lc][6]*y.z + as[lc][7]*y.w;
        sm[OFF_E3 + wt] = ce * pe;
    }
    // lvl3 down (group 0; E3 produced/consumed by same threads)
    if (q == 0) {
        int t = s >> 1;
        int half = s & 1;
        float eps3 = sm[OFF_E3 + wt];
        float pe3 = __fdividef(eps3, g_sbeta3[t*128 + wt]);
        if (half == 0) acc += eps3 * g_lbt[g*2048 + slab[192]*8 + i];
        #pragma unroll
        for (int l = 0; l < 4; l++) {
            float ce, ca;
            dot_dn(&g_beta4[(4*t + l)*128], as, la, g, l, ce, ca);
            ce *= pe3;
            int lown = l - 2*half;
            if (lown == 0 || lown == 1) {
                acc += pe3*ca + lsp[l]*ce;
                sm[OFF_E4 + lown*128 + wt] = ce;
            }
        }
    }
    __syncthreads();

    // ================= phase 3: pair-of-subtrees down =================
    if (q < 2) {
        float epsv = sm[OFF_E4 + q*128 + wt];
        float pe = __fdividef(epsv, sm[OFF_S4 + q*128 + wt]);
        acc += epsv * g_lbt[g*2048 + slab[168 + q]*8 + i];
        #pragma unroll
        for (int l = 0; l < 4; l++) {
            float ce, ca;
            dot_dn(sm + OFF_B5 + (4*q + l)*128, as, la, g, l, ce, ca);
            ce *= pe;
            sm[OFF_E5 + (4*q + l)*128 + wt] = ce;
            acc += pe*ca + lsp[l]*ce;
        }
    }
    __syncthreads();
    // lvl5 down (8)
    #pragma unroll
    for (int rr = 0; rr < 2; rr++) {
        int k = rr*4 + q;
        float epsv = sm[OFF_E5 + k*128 + wt];
        float pe = __fdividef(epsv, sm[OFF_S5 + k*128 + wt]);
        acc += epsv * g_lbt[g*2048 + slab[160 + k]*8 + i];
        #pragma unroll
        for (int l = 0; l < 4; l++) {
            float ce, ca;
            dot_dn(sm + OFF_B6 + (4*k + l)*128, as, la, g, l, ce, ca);
            ce *= pe;
            sm[OFF_E6 + (4*k + l)*128 + wt] = ce;
            acc += pe*ca + lsp[l]*ce;
        }
    }
    __syncthreads();
    // wait dntab complete (normally already satisfied)
    if (tid == 0) {
        while (ld_acquire(&g_cdn) != (unsigned)NBLK) {}
    }
    __syncthreads();
    // lvl6 down (32): leaf children via dn_tab, emission prefetch
    float lemis6[8];
    #pragma unroll
    for (int rr = 0; rr < 8; rr++)
        lemis6[rr] = g_lbt[g*2048 + slab[128 + rr*4 + q]*8 + i];
    #pragma unroll 4
    for (int rr = 0; rr < 8; rr++) {
        int k = rr*4 + q;
        int lab0 = slab[4*k], lab1 = slab[4*k+1], lab2 = slab[4*k+2], lab3 = slab[4*k+3];
        float epsv = sm[OFF_E6 + k*128 + wt];
        float pe = __fdividef(epsv, sm[OFF_S6 + k*128 + wt]);
        acc += epsv * lemis6[rr];
        float d = g_dntab[(0*256 + lab0)*128 + wt]
                + g_dntab[(1*256 + lab1)*128 + wt]
                + g_dntab[(2*256 + lab2)*128 + wt]
                + g_dntab[(3*256 + lab3)*128 + wt];
        acc += pe * d;
    }

    // ================= reduce + finish ticket =================
    acc = sum8(acc);
    if (i == 0) sm[OFF_RED + q*16 + g] = acc;
    __syncthreads();
    if (tid < 16) {
        float p = sm[OFF_RED + tid] + sm[OFF_RED + 16 + tid]
                + sm[OFF_RED + 32 + tid] + sm[OFF_RED + 48 + tid];
        atomicAdd(&g_accum[tid], p);
    }
    __syncthreads();
    unsigned* plast = (unsigned*)(sm + OFF_LAST);
    if (tid == 0) {
        unsigned old = atom_acqrel_add(&g_cfin, 1u);
        *plast = (old == NBLK - 1u) ? 1u : 0u;
    }
    __syncthreads();
    if (*plast && tid < 16)
        out[tid] = *(volatile float*)&g_accum[tid];
}

// ---------------------------------------------------------------------------
extern "C" void kernel_launch(void* const* d_in, const int* in_sizes, int n_in,
                              void* d_out, int out_size)
{
    const int*   tn = (const int*)  d_in[0];
    const float* a  = (const float*)d_in[2];
    const float* b  = (const float*)d_in[3];
    const float* pi = (const float*)d_in[4];
    const float* sp = (const float*)d_in[5];
    float* out = (float*)d_out;

    cudaFuncSetAttribute(main_kernel,
                         cudaFuncAttributeMaxDynamicSharedMemorySize,
                         SMEM_FLOATS * 4);
    main_kernel<<<NBLK, 512, SMEM_FLOATS * 4>>>(tn, a, b, pi, sp, out);
}